// round 17
// baseline (speedup 1.0000x reference)
#include <cuda_runtime.h>
#include <cuda_fp16.h>
#include <cstdint>

#define BB   4
#define CC   256
#define HH   64
#define WW   64
#define HWS  4096
#define NP   9
#define OCH  18
#define OPL  256
#define KTOT 2304
#define MTOT 16384        // B*H*W

#define MT     128        // GEMM M tile
#define NCHUNK 72         // chunks: (kernel point k, 32-channel group)
#define NTH    512
#define AS8    132        // sA row stride in 8B units
#define BS8    12         // sB row stride in 8B units
#define NSTAGE 3

#define CVT_BLOCKS 1024   // x -> fp16: 4,194,304 floats / 4096 per block

// ---- dynamic smem for GEMM ----
#define SA_BYTES (8 * AS8 * 8)             // 8448
#define SB_BYTES (256 * BS8 * 8)           // 24576
#define SM_SB0   (NSTAGE * SA_BYTES)
#define SM_TOTAL (NSTAGE * (SA_BYTES + SB_BYTES))   // 99072

typedef unsigned long long ull;

__device__ float4 g_mw[BB * HWS * NP];
__device__ int4   g_mi[BB * HWS * NP];
__device__ __half g_wB[OPL * KTOT];        // [n][chunk*32 + phys-k], fp16
__device__ __half g_x16[(size_t)BB * CC * HWS];   // fp16 copy of x
// A: [chunk][gt-row(8)][pos] of 8B = 4 fp16 {2t,2t+1,2t+8,2t+9}
__device__ ull    g_A2[(size_t)NCHUNK * 8 * MTOT];

// ---------------------------------------------------------------------------
// helpers
// ---------------------------------------------------------------------------
__device__ __forceinline__ ull dup2(float v) {
    ull r; asm("mov.b64 %0, {%1, %1};" : "=l"(r) : "f"(v)); return r;
}
__device__ __forceinline__ ull pack2(float a, float b) {
    ull r; asm("mov.b64 %0, {%1, %2};" : "=l"(r) : "f"(a), "f"(b)); return r;
}
__device__ __forceinline__ void fma2(ull& acc, ull a, ull b) {
    asm("fma.rn.f32x2 %0, %1, %2, %0;" : "+l"(acc) : "l"(a), "l"(b));
}
union UPair { ull u; float2 f; };

__device__ __forceinline__ uint32_t smem_u32(const void* p) {
    return (uint32_t)__cvta_generic_to_shared(p);
}
__device__ __forceinline__ void cpa16(void* dst, const void* src) {
    asm volatile("cp.async.cg.shared.global [%0], [%1], 16;"
                 :: "r"(smem_u32(dst)), "l"(src));
}
__device__ __forceinline__ void cpa_commit() {
    asm volatile("cp.async.commit_group;" ::: "memory");
}
template <int N>
__device__ __forceinline__ void cpa_wait_group() {
    asm volatile("cp.async.wait_group %0;" :: "n"(N) : "memory");
}

__device__ __forceinline__ void mma_f16(float* c, const uint32_t* a, const uint32_t* b) {
    asm volatile(
        "mma.sync.aligned.m16n8k16.row.col.f32.f16.f16.f32 "
        "{%0,%1,%2,%3}, {%4,%5,%6,%7}, {%8,%9}, {%0,%1,%2,%3};"
        : "+f"(c[0]), "+f"(c[1]), "+f"(c[2]), "+f"(c[3])
        : "r"(a[0]), "r"(a[1]), "r"(a[2]), "r"(a[3]), "r"(b[0]), "r"(b[1]));
}

__device__ __forceinline__ float dot4h(float4 wv, const __half* xp, int4 iv) {
    return wv.x * __half2float(xp[iv.x]) + wv.y * __half2float(xp[iv.y])
         + wv.z * __half2float(xp[iv.z]) + wv.w * __half2float(xp[iv.w]);
}

// ---------------------------------------------------------------------------
// Kernel 1 (fused prep):
//   blocks [0,256):            offsets conv + metadata (shuffle tap-sharing)
//   blocks [256,256+1024):     x -> fp16 conversion
//   blocks [256+1024, +1152):  w_conv permute -> fp16 g_wB
// ---------------------------------------------------------------------------
__global__ __launch_bounds__(512) void prep_kernel(const float* __restrict__ x,
                                                   const float* __restrict__ w_p,
                                                   const float* __restrict__ wc)
{
    if (blockIdx.x >= 256 + CVT_BLOCKS) {
        int idx = (blockIdx.x - 256 - CVT_BLOCKS) * 512 + threadIdx.x;
        if (idx < OPL * KTOT) {
            int n  = idx / KTOT;
            int rp = idx - n * KTOT;
            int chunk = rp >> 5;
            int p   = rp & 31;
            int g   = p >> 4;
            int p16 = p & 15;
            int t   = p16 >> 2;
            int j   = p16 & 3;
            int kl  = (j < 2) ? (2 * t + j) : (8 + 2 * t + (j - 2));
            int c   = (chunk & 7) * 32 + g * 16 + kl;
            int k   = chunk >> 3;
            g_wB[idx] = __float2half_rn(wc[n * KTOT + c * 9 + k]);
        }
        return;
    }
    if (blockIdx.x >= 256) {
        // x -> fp16: 4096 floats per block, 8 per thread
        int base = (blockIdx.x - 256) * 4096 + threadIdx.x * 8;
        float4 a = *(const float4*)(x + base);
        float4 c = *(const float4*)(x + base + 4);
        __half2 p0 = __floats2half2_rn(a.x, a.y);
        __half2 p1 = __floats2half2_rn(a.z, a.w);
        __half2 p2 = __floats2half2_rn(c.x, c.y);
        __half2 p3 = __floats2half2_rn(c.z, c.w);
        uint4 st;
        st.x = *(uint32_t*)&p0; st.y = *(uint32_t*)&p1;
        st.z = *(uint32_t*)&p2; st.w = *(uint32_t*)&p3;
        *(uint4*)(g_x16 + base) = st;
        return;
    }

    __shared__ ull s_mem[64 * 9 * 10];

    const int tid   = threadIdx.x;
    const int lane  = tid & 31;
    const int pos_l = tid & 63;
    const int part  = tid >> 6;                 // 0..7
    const int pos   = blockIdx.x * 64 + pos_l;
    const int b = pos >> 12;
    const int h = (pos >> 6) & 63;
    const int w = pos & 63;
    const float* xb = x + (size_t)b * CC * HWS;

    ull accp[9];
#pragma unroll
    for (int i = 0; i < 9; i++) accp[i] = 0ull;

    for (int blk = 0; blk < 4; blk++) {
        __syncthreads();
        for (int i = tid; i < 64 * 81; i += 512) {
            int cl = i / 81;
            int r  = i % 81;
            int t  = r / 9;
            int op = r - t * 9;
            int c  = blk * 64 + cl;
            float w0 = w_p[((2 * op)     * CC + c) * 9 + t];
            float w1 = w_p[((2 * op + 1) * CC + c) * 9 + t];
            s_mem[(cl * 9 + t) * 10 + op] = pack2(w0, w1);
        }
        __syncthreads();

        for (int q = 0; q < 8; q++) {
            int cl = part * 8 + q;
            const float* xp = xb + (size_t)(blk * 64 + cl) * HWS;
            float xv[9];
            // rows via warp shuffle: 1 main LDG + 2-lane edge LDG per row
#pragma unroll
            for (int r = 0; r < 3; r++) {
                int gh = h - 1 + r;
                bool vr = (unsigned)gh < 64u;
                const float* rowp = xp + gh * 64;
                float v = vr ? rowp[w] : 0.f;
                float lf = __shfl_up_sync(0xffffffffu, v, 1);
                float rt = __shfl_down_sync(0xffffffffu, v, 1);
                if (lane == 0)  lf = (vr && w > 0)  ? rowp[w - 1] : 0.f;
                if (lane == 31) rt = (vr && w < 63) ? rowp[w + 1] : 0.f;
                xv[r * 3 + 0] = lf;
                xv[r * 3 + 1] = v;
                xv[r * 3 + 2] = rt;
            }
#pragma unroll
            for (int t = 0; t < 9; t++) {
                ull xd = dup2(xv[t]);
                const ulonglong2* wp4 = (const ulonglong2*)&s_mem[(cl * 9 + t) * 10];
                ulonglong2 p01 = wp4[0];
                ulonglong2 p23 = wp4[1];
                ulonglong2 p45 = wp4[2];
                ulonglong2 p67 = wp4[3];
                ull p8 = s_mem[(cl * 9 + t) * 10 + 8];
                fma2(accp[0], p01.x, xd);
                fma2(accp[1], p01.y, xd);
                fma2(accp[2], p23.x, xd);
                fma2(accp[3], p23.y, xd);
                fma2(accp[4], p45.x, xd);
                fma2(accp[5], p45.y, xd);
                fma2(accp[6], p67.x, xd);
                fma2(accp[7], p67.y, xd);
                fma2(accp[8], p8,    xd);
            }
        }
    }

    __syncthreads();
    ull* s_red = s_mem;
#pragma unroll
    for (int op = 0; op < 9; op++)
        s_red[(part * 64 + pos_l) * 9 + op] = accp[op];
    __syncthreads();

    if (tid < 64) {
        float acc[OCH];
#pragma unroll
        for (int op = 0; op < 9; op++) {
            float sx = 0.f, sy = 0.f;
#pragma unroll
            for (int pt = 0; pt < 8; pt++) {
                UPair u; u.u = s_red[(pt * 64 + tid) * 9 + op];
                sx += u.f.x; sy += u.f.y;
            }
            acc[2 * op]     = sx;
            acc[2 * op + 1] = sy;
        }
#pragma unroll
        for (int k = 0; k < 9; k++) {
            float rx = (float)(k / 3 - 1);
            float ry = (float)(k % 3 - 1);
            float px = acc[k]     + rx + (float)(h + 1);
            float py = acc[9 + k] + ry + (float)(w + 1);
            float fx = floorf(px), fy = floorf(py);
            float ltx = fminf(fmaxf(fx,       0.f), 63.f);
            float lty = fminf(fmaxf(fy,       0.f), 63.f);
            float rbx = fminf(fmaxf(fx + 1.f, 0.f), 63.f);
            float rby = fminf(fmaxf(fy + 1.f, 0.f), 63.f);
            float pxc = fminf(fmaxf(px,       0.f), 63.f);
            float pyc = fminf(fmaxf(py,       0.f), 63.f);
            float glt = (1.f + (ltx - pxc)) * (1.f + (lty - pyc));
            float grb = (1.f - (rbx - pxc)) * (1.f - (rby - pyc));
            float glb = (1.f + (ltx - pxc)) * (1.f - (rby - pyc));
            float grt = (1.f - (rbx - pxc)) * (1.f + (lty - pyc));
            int iltx = (int)ltx, ilty = (int)lty, irbx = (int)rbx, irby = (int)rby;
            g_mw[pos * 9 + k] = make_float4(glt, grb, glb, grt);
            g_mi[pos * 9 + k] = make_int4(iltx * WW + ilty,
                                          irbx * WW + irby,
                                          iltx * WW + irby,
                                          irbx * WW + ilty);
        }
    }
}

// ---------------------------------------------------------------------------
// Kernel 2: gather — fp16 A from fp16 x (half the L1 line traffic)
// ---------------------------------------------------------------------------
__global__ __launch_bounds__(1024) void gather_kernel()
{
    const int tid  = threadIdx.x;
    const int warp = tid >> 5;
    const int lane = tid & 31;
    const int pw   = warp & 3;
    const int cs   = warp >> 2;        // 0..7: 32-channel group
    const int pos  = blockIdx.x * 128 + pw * 32 + lane;
    const int b    = pos >> 12;
    const __half* xb = g_x16 + (size_t)b * CC * HWS;

    for (int k = 0; k < 9; k++) {
        const float4 wv = g_mw[pos * NP + k];
        const int4   iv = g_mi[pos * NP + k];
        const int chunk = k * 8 + cs;
        ull* cb = g_A2 + (size_t)chunk * 8 * MTOT + pos;
        const __half* xp = xb + (size_t)(cs * 32) * HWS;
#pragma unroll
        for (int gt = 0; gt < 8; gt++) {
            const int g = gt >> 2;
            const int t = gt & 3;
            const __half* xc = xp + (size_t)(g * 16 + 2 * t) * HWS;
            float f0 = dot4h(wv, xc,           iv);
            float f1 = dot4h(wv, xc + HWS,     iv);
            float f2 = dot4h(wv, xc + 8 * HWS, iv);
            float f3 = dot4h(wv, xc + 9 * HWS, iv);
            __half2 h01 = __floats2half2_rn(f0, f1);
            __half2 h23 = __floats2half2_rn(f2, f3);
            uint2 st;
            st.x = *(uint32_t*)&h01;
            st.y = *(uint32_t*)&h23;
            *(uint2*)(cb + (size_t)gt * MTOT) = st;
        }
    }
}

// ---------------------------------------------------------------------------
// Kernel 3: dense fp16 GEMM (m16n8k16, f32 accum), 3-stage cp.async pipeline
// ---------------------------------------------------------------------------
__global__ void __launch_bounds__(NTH, 1) gemm_kernel(float* __restrict__ out)
{
    extern __shared__ char smem[];

    const int tid  = threadIdx.x;
    const int wid  = tid >> 5;
    const int lane = tid & 31;
    const int gid  = lane >> 2;
    const int tig  = lane & 3;
    const int p0   = blockIdx.x * MT;
    const int b    = p0 >> 12;
    const int m0   = p0;

    const int mBase = (wid & 3) * 32;
    const int nBase = (wid >> 2) * 64;

    auto issue_stage = [&](int i, int s) {
        char* sa = smem + s * SA_BYTES;
        char* sb = smem + SM_SB0 + s * SB_BYTES;
        const ull* aChunk = g_A2 + (size_t)i * 8 * MTOT + m0;
        const __half* bChunk = g_wB + i * 32;
        {
            int r = tid >> 6;
            int q = tid & 63;
            cpa16(sa + r * (AS8 * 8) + q * 16, aChunk + (size_t)r * MTOT + q * 2);
        }
#pragma unroll
        for (int r = 0; r < 2; r++) {
            int id = tid + r * NTH;
            int nr = id >> 2;
            int q  = id & 3;
            cpa16(sb + nr * (BS8 * 8) + q * 16, bChunk + (size_t)nr * KTOT + q * 8);
        }
        cpa_commit();
    };

    float acc[2][8][4];
#pragma unroll
    for (int mf = 0; mf < 2; mf++)
#pragma unroll
        for (int nf = 0; nf < 8; nf++)
#pragma unroll
            for (int r = 0; r < 4; r++) acc[mf][nf][r] = 0.f;

    issue_stage(0, 0);
    issue_stage(1, 1);

    for (int i = 0; i < NCHUNK; i++) {
        const int s = i % NSTAGE;
        cpa_wait_group<1>();
        __syncthreads();

        if (i + 2 < NCHUNK) issue_stage(i + 2, (i + 2) % NSTAGE);
        else                cpa_commit();

        const ull* sA8 = (const ull*)(smem + s * SA_BYTES);
        const ull* sB8 = (const ull*)(smem + SM_SB0 + s * SB_BYTES);
#pragma unroll
        for (int g = 0; g < 2; g++) {
            uint32_t a[2][4], bfrag[8][2];
#pragma unroll
            for (int mf = 0; mf < 2; mf++) {
                int m = mBase + mf * 16 + gid;
                uint2 v0 = *(const uint2*)&sA8[(g * 4 + tig) * AS8 + m];
                uint2 v1 = *(const uint2*)&sA8[(g * 4 + tig) * AS8 + m + 8];
                a[mf][0] = v0.x;
                a[mf][1] = v1.x;
                a[mf][2] = v0.y;
                a[mf][3] = v1.y;
            }
#pragma unroll
            for (int nf = 0; nf < 8; nf++) {
                int n = nBase + nf * 8 + gid;
                uint2 bv = *(const uint2*)&sB8[n * BS8 + g * 4 + tig];
                bfrag[nf][0] = bv.x;
                bfrag[nf][1] = bv.y;
            }
#pragma unroll
            for (int mf = 0; mf < 2; mf++)
#pragma unroll
                for (int nf = 0; nf < 8; nf++)
                    mma_f16(acc[mf][nf], a[mf], bfrag[nf]);
        }
    }

    // ---- epilogue ----
    {
        const int hw0 = p0 & 4095;
        float* ob = out + (size_t)b * OPL * HWS + hw0;
#pragma unroll
        for (int mf = 0; mf < 2; mf++) {
            int m = mBase + mf * 16 + gid;
#pragma unroll
            for (int nf = 0; nf < 8; nf++) {
                int n = nBase + nf * 8 + 2 * tig;
                ob[(size_t)n * HWS + m]           = acc[mf][nf][0];
                ob[(size_t)(n + 1) * HWS + m]     = acc[mf][nf][1];
                ob[(size_t)n * HWS + m + 8]       = acc[mf][nf][2];
                ob[(size_t)(n + 1) * HWS + m + 8] = acc[mf][nf][3];
            }
        }
    }
}

// ---------------------------------------------------------------------------
extern "C" void kernel_launch(void* const* d_in, const int* in_sizes, int n_in,
                              void* d_out, int out_size)
{
    const float* x      = (const float*)d_in[0];   // (4,256,64,64)
    const float* w_p    = (const float*)d_in[1];   // (18,256,3,3)
    const float* w_conv = (const float*)d_in[2];   // (256,256,3,3)
    float* out = (float*)d_out;                    // (4,256,64,64)

    cudaFuncSetAttribute(gemm_kernel, cudaFuncAttributeMaxDynamicSharedMemorySize, SM_TOTAL);

    const int permBlocks = (OPL * KTOT + 511) / 512;
    prep_kernel<<<256 + CVT_BLOCKS + permBlocks, 512>>>(x, w_p, w_conv);
    gather_kernel<<<MTOT / 128, 1024>>>();
    gemm_kernel<<<MTOT / MT, NTH, SM_TOTAL>>>(out);
}